// round 16
// baseline (speedup 1.0000x reference)
#include <cuda_runtime.h>
#include <cuda_bf16.h>
#include <math.h>
#include <cstdint>

// ---------------- problem constants ----------------
#define HH     112
#define WW     112
#define CC     128
#define SHIFT3 3
#define NH4    4
#define BB     8
#define HID    512
#define NN     49
#define HD32   32
#define NW     256
#define LTOK   (HH*WW)      // 12544
#define MROWS  (BB*NW*NN)   // 100352 = 784*128
#define SCALEF 0.17677669529663687f

// ---------------- scratch ----------------
__device__ __nv_bfloat16 g_obuf_bf[MROWS*CC];
__device__ __nv_bfloat16 g_y_bf   [MROWS*CC];
__device__ __nv_bfloat16 g_h1_bf  [MROWS*HID];
__device__ __nv_bfloat16 g_q_bf   [MROWS*CC];
__device__ __nv_bfloat16 g_k_bf   [MROWS*CC];
__device__ __nv_bfloat16 g_v_bf   [MROWS*CC];
__device__ float g_xres[MROWS*CC];
__device__ __nv_bfloat16 g_qkvw[3*CC*CC];
__device__ __nv_bfloat16 g_projw[CC*CC];
__device__ __nv_bfloat16 g_fc1w[HID*CC];
__device__ __nv_bfloat16 g_fc2w[CC*HID];
__device__ float g_atbl[4*4*64*64];   // [type][head][n][m] bias+mask (+pad=-1e9)

// ---------------- helpers ----------------
__device__ __forceinline__ uint32_t smem_u32(const void* p) {
    uint32_t a;
    asm("{ .reg .u64 t; cvta.to.shared.u64 t, %1; cvt.u32.u64 %0, t; }" : "=r"(a) : "l"(p));
    return a;
}
__device__ __forceinline__ uint32_t pack_bf2(float lo, float hi) {
    __nv_bfloat162 v = __floats2bfloat162_rn(lo, hi);
    return *(uint32_t*)&v;
}
// fast gelu: tanh form via __expf (exact-erf deviation < ~3e-4 abs)
__device__ __forceinline__ float gelu_f(float x) {
    float u = x * (0.7978845608028654f + 0.0356774081f * (x * x));
    float e = __expf(2.0f * u);
    float th = 1.0f - 2.0f / (e + 1.0f);
    return 0.5f * x * (1.0f + th);
}
__device__ __forceinline__ void mma_bf16(float& c0, float& c1, float& c2, float& c3,
                                         uint32_t a0, uint32_t a1, uint32_t a2, uint32_t a3,
                                         uint32_t b0, uint32_t b1) {
    asm volatile("mma.sync.aligned.m16n8k16.row.col.f32.bf16.bf16.f32 "
                 "{%0,%1,%2,%3}, {%4,%5,%6,%7}, {%8,%9}, {%0,%1,%2,%3};"
                 : "+f"(c0), "+f"(c1), "+f"(c2), "+f"(c3)
                 : "r"(a0), "r"(a1), "r"(a2), "r"(a3), "r"(b0), "r"(b1));
}
#define LDSM4(r0, r1, r2, r3, addr) \
    asm volatile("ldmatrix.sync.aligned.m8n8.x4.shared.b16 {%0,%1,%2,%3}, [%4];" \
                 : "=r"(r0), "=r"(r1), "=r"(r2), "=r"(r3) : "r"(addr))
#define LDSM4T(r0, r1, r2, r3, addr) \
    asm volatile("ldmatrix.sync.aligned.m8n8.x4.trans.shared.b16 {%0,%1,%2,%3}, [%4];" \
                 : "=r"(r0), "=r"(r1), "=r"(r2), "=r"(r3) : "r"(addr))
#define CP_ASYNC16(dst, src) \
    asm volatile("cp.async.cg.shared.global [%0], [%1], 16;" :: "r"(dst), "l"(src))
#define CP_COMMIT() asm volatile("cp.async.commit_group;" ::: "memory")
#define CP_WAIT0()  asm volatile("cp.async.wait_group 0;" ::: "memory")
#define CP_WAIT1()  asm volatile("cp.async.wait_group 1;" ::: "memory")
#define CP_WAIT2()  asm volatile("cp.async.wait_group 2;" ::: "memory")

__device__ __forceinline__ int tok_of(int m) {
    int bn = m / NN, n = m - bn * NN;
    int bi = bn >> 8, win = bn & 255;
    int wi = win >> 4, wj = win & 15;
    int r = n / 7, cq = n - r * 7;
    int ii = wi * 7 + r + SHIFT3;  if (ii >= HH) ii -= HH;
    int jj = wj * 7 + cq + SHIFT3; if (jj >= WW) jj -= WW;
    return bi * LTOK + ii * WW + jj;
}
__device__ __forceinline__ int regionf(int i) { return (i < 105) ? 0 : ((i < 109) ? 1 : 2); }

// ---------------- merged setup: weight cvt + attention table ----------------
__global__ void setup_kernel(const float* __restrict__ qkv, const float* __restrict__ proj,
                             const float* __restrict__ fc1, const float* __restrict__ fc2,
                             const float* __restrict__ rpb) {
    int b = blockIdx.x;
    if (b < 192) {
        int i = (b * 256 + threadIdx.x) * 4;
        const float* src;
        __nv_bfloat16* dst;
        int off;
        if (i < 49152)       { src = qkv;  dst = g_qkvw;  off = i; }
        else if (i < 65536)  { src = proj; dst = g_projw; off = i - 49152; }
        else if (i < 131072) { src = fc1;  dst = g_fc1w;  off = i - 65536; }
        else                 { src = fc2;  dst = g_fc2w;  off = i - 131072; }
        float4 v = *(const float4*)(src + off);
        uint2 pk;
        pk.x = pack_bf2(v.x, v.y);
        pk.y = pack_bf2(v.z, v.w);
        *(uint2*)(dst + off) = pk;
    } else {
        int i = (b - 192) * 256 + threadIdx.x;   // 65536 entries
        int m = i & 63, n = (i >> 6) & 63, h = (i >> 12) & 3, ty = i >> 14;
        float v;
        if (n < NN && m < NN) {
            int r1 = n / 7, c1 = n % 7, r2 = m / 7, c2 = m % 7;
            int wiq = (ty >> 1) ? 15 : 0, wjq = (ty & 1) ? 15 : 0;
            int reg1 = regionf(wiq * 7 + r1) * 3 + regionf(wjq * 7 + c1);
            int reg2 = regionf(wiq * 7 + r2) * 3 + regionf(wjq * 7 + c2);
            v = rpb[((r1 - r2 + 6) * 13 + (c1 - c2 + 6)) * NH4 + h];
            if (reg1 != reg2) v -= 100.0f;
        } else {
            v = -1e9f;
        }
        g_atbl[i] = v;
    }
}

// =====================================================================
// GEMM machinery: 128x128 tile, 8 warps (4m x 2n), ldmatrix + mma
// =====================================================================
#define SM_PROJ 73728
#define SM_STG  73728       // staging region offset (qkv/fc1)
#define SM_QKV  108544      // 73728 + 128*272
#define SM_FC1  108544
#define SM_FC2  110592      // 3 x 36864

__device__ __forceinline__ void zero_acc(float acc[2][8][4]) {
    #pragma unroll
    for (int mi = 0; mi < 2; ++mi)
        #pragma unroll
        for (int ni = 0; ni < 8; ++ni)
            #pragma unroll
            for (int q = 0; q < 4; ++q) acc[mi][ni][q] = 0.0f;
}

__device__ __forceinline__ void gemm_chunk_mma(
    float acc[2][8][4], uint32_t Ab, uint32_t Bb,
    int wm, int wn, uint32_t a_lane_off, uint32_t b_lane_off) {
    #pragma unroll
    for (int kk2 = 0; kk2 < 32; kk2 += 8) {
        uint32_t af[2][4];
        #pragma unroll
        for (int mi = 0; mi < 2; ++mi)
            LDSM4(af[mi][0], af[mi][1], af[mi][2], af[mi][3],
                  Ab + (wm + mi * 16) * 144 + kk2 * 4 + a_lane_off);
        uint32_t bf[8][2];
        #pragma unroll
        for (int p = 0; p < 4; ++p)
            LDSM4(bf[2*p][0], bf[2*p][1], bf[2*p+1][0], bf[2*p+1][1],
                  Bb + (wn + p * 16) * 144 + kk2 * 4 + b_lane_off);
        #pragma unroll
        for (int mi = 0; mi < 2; ++mi)
            #pragma unroll
            for (int ni = 0; ni < 8; ++ni)
                mma_bf16(acc[mi][ni][0], acc[mi][ni][1], acc[mi][ni][2], acc[mi][ni][3],
                         af[mi][0], af[mi][1], af[mi][2], af[mi][3],
                         bf[ni][0], bf[ni][1]);
    }
}

// write acc (+bias, optional gelu/scale) into 272B-stride staging tile
template<bool GELU>
__device__ __forceinline__ void stage_acc(
    char* smem, float acc[2][8][4], const float* bias_blk, float scl,
    int wm, int wn, int g, int t) {
    #pragma unroll
    for (int mi = 0; mi < 2; ++mi)
        #pragma unroll
        for (int half = 0; half < 2; ++half) {
            int row = wm + mi * 16 + g + half * 8;
            #pragma unroll
            for (int ni = 0; ni < 8; ++ni) {
                int ol = wn + ni * 8 + 2 * t;
                float a = acc[mi][ni][half*2+0] + bias_blk[ol];
                float b = acc[mi][ni][half*2+1] + bias_blk[ol + 1];
                if (GELU) {
                    a = gelu_f(a);
                    b = gelu_f(b);
                } else {
                    a *= scl; b *= scl;
                }
                *(uint32_t*)(smem + SM_STG + row * 272 + ol * 2) = pack_bf2(a, b);
            }
        }
}

// ---------------- QKV GEMM with fused LN1 gather; staged wide stores -----------
__global__ void __launch_bounds__(256, 2)
gemm_qkv(const float* __restrict__ bias, const float* __restrict__ xin,
         const float* __restrict__ n1w, const float* __restrict__ n1b) {
    extern __shared__ char smem[];
    const uint32_t sbase = smem_u32(smem);
    const int m0 = blockIdx.x * 128;
    const int tid  = threadIdx.x;
    const int wid  = tid >> 5;
    const int lane = tid & 31;
    const int g = lane >> 2;
    const int t = lane & 3;
    const int wm = (wid >> 1) * 32;
    const int wn = (wid & 1) * 64;
    const uint32_t a_lane_off = ((lane & 7) + ((lane >> 3) & 1) * 8) * 144 + (lane >> 4) * 16;
    const uint32_t b_lane_off = (((lane >> 4) & 1) * 8 + (lane & 7)) * 144 + ((lane >> 3) & 1) * 16;

    #pragma unroll
    for (int it = 0; it < 4; ++it) {
        int idx = tid + it * 256;
        int r = idx >> 3, cc2 = idx & 7;
        CP_ASYNC16(sbase + 36864 + r * 144 + cc2 * 16, g_qkvw + (size_t)r * 128 + cc2 * 8);
    }
    CP_COMMIT();

    // fused LN1 + shift-gather into A tile
    {
        float4 wv = ((const float4*)n1w)[lane];
        float4 bv = ((const float4*)n1b)[lane];
        #pragma unroll 4
        for (int rr = 0; rr < 16; ++rr) {
            int r = wid * 16 + rr;
            int tok = tok_of(m0 + r);
            float4 v = *(const float4*)(xin + (size_t)tok * CC + lane * 4);
            float s = v.x + v.y + v.z + v.w;
            #pragma unroll
            for (int o = 16; o; o >>= 1) s += __shfl_xor_sync(0xffffffffu, s, o);
            float mean = s * (1.0f / 128.0f);
            float dx = v.x - mean, dy = v.y - mean, dz = v.z - mean, dw = v.w - mean;
            float q = dx*dx + dy*dy + dz*dz + dw*dw;
            #pragma unroll
            for (int o = 16; o; o >>= 1) q += __shfl_xor_sync(0xffffffffu, q, o);
            float inv = rsqrtf(q * (1.0f / 128.0f) + 1e-5f);
            uint2 pk;
            pk.x = pack_bf2(dx * inv * wv.x + bv.x, dy * inv * wv.y + bv.y);
            pk.y = pack_bf2(dz * inv * wv.z + bv.z, dw * inv * wv.w + bv.w);
            *(uint2*)(smem + (lane >> 4) * 18432 + r * 144 + (lane & 15) * 8) = *(uint2*)&pk;
        }
    }

    float acc[2][8][4];
    #pragma unroll 1
    for (int s = 0; s < 6; ++s) {
        int c = s & 1, yb = s >> 1;
        if (c == 0) zero_acc(acc);
        if (s + 1 < 6) {
            int yb2 = (s + 1) >> 1, c2 = (s + 1) & 1;
            #pragma unroll
            for (int it = 0; it < 4; ++it) {
                int idx = tid + it * 256;
                int r = idx >> 3, cc2 = idx & 7;
                CP_ASYNC16(sbase + 36864 + ((s + 1) & 1) * 18432 + r * 144 + cc2 * 16,
                           g_qkvw + (size_t)(yb2 * 128 + r) * 128 + c2 * 64 + cc2 * 8);
            }
            CP_COMMIT();
            CP_WAIT1();
        } else {
            CP_WAIT0();
        }
        __syncthreads();
        gemm_chunk_mma(acc, sbase + c * 18432, sbase + 36864 + (s & 1) * 18432,
                       wm, wn, a_lane_off, b_lane_off);
        __syncthreads();
        if (c == 1) {
            __nv_bfloat16* dst = (yb == 0) ? g_q_bf : (yb == 1) ? g_k_bf : g_v_bf;
            stage_acc<false>(smem, acc, bias + yb * 128, (yb == 0) ? SCALEF : 1.0f,
                             wm, wn, g, t);
            __syncthreads();
            // cooperative wide stores: 128 rows x 16 uint4 segments
            #pragma unroll
            for (int it = 0; it < 8; ++it) {
                int idx = tid + it * 256;
                int row = idx >> 4, seg = idx & 15;
                uint4 v = *(const uint4*)(smem + SM_STG + row * 272 + seg * 16);
                int m = m0 + row;
                int bn = m / NN, n = m - bn * NN;
                int hh = seg >> 2, dd = (seg & 3) * 8;
                *(uint4*)(dst + (size_t)(bn * NH4 + hh) * (NN * HD32) + n * HD32 + dd) = v;
            }
            __syncthreads();
        }
    }
}

// ---------------- fc1 GEMM: A resident, 4 weight blocks, gelu, staged stores ---
__global__ void __launch_bounds__(256, 2)
gemm_fc1(const float* __restrict__ bias) {
    extern __shared__ char smem[];
    const uint32_t sbase = smem_u32(smem);
    const int m0 = blockIdx.x * 128;
    const int tid  = threadIdx.x;
    const int wid  = tid >> 5;
    const int lane = tid & 31;
    const int g = lane >> 2;
    const int t = lane & 3;
    const int wm = (wid >> 1) * 32;
    const int wn = (wid & 1) * 64;
    const uint32_t a_lane_off = ((lane & 7) + ((lane >> 3) & 1) * 8) * 144 + (lane >> 4) * 16;
    const uint32_t b_lane_off = (((lane >> 4) & 1) * 8 + (lane & 7)) * 144 + ((lane >> 3) & 1) * 16;

    #pragma unroll
    for (int it = 0; it < 8; ++it) {
        int idx = tid + it * 256;
        int r = idx >> 4, cc = idx & 15;
        CP_ASYNC16(sbase + (cc >> 3) * 18432 + r * 144 + (cc & 7) * 16,
                   g_y_bf + (size_t)(m0 + r) * 128 + cc * 8);
    }
    #pragma unroll
    for (int it = 0; it < 4; ++it) {
        int idx = tid + it * 256;
        int r = idx >> 3, cc2 = idx & 7;
        CP_ASYNC16(sbase + 36864 + r * 144 + cc2 * 16, g_fc1w + (size_t)r * 128 + cc2 * 8);
    }
    CP_COMMIT();

    float acc[2][8][4];
    #pragma unroll 1
    for (int s = 0; s < 8; ++s) {
        int c = s & 1, yb = s >> 1;
        if (c == 0) zero_acc(acc);
        if (s + 1 < 8) {
            int yb2 = (s + 1) >> 1, c2 = (s + 1) & 1;
            #pragma unroll
            for (int it = 0; it < 4; ++it) {
                int idx = tid + it * 256;
                int r = idx >> 3, cc2 = idx & 7;
                CP_ASYNC16(sbase + 36864 + ((s + 1) & 1) * 18432 + r * 144 + cc2 * 16,
                           g_fc1w + (size_t)(yb2 * 128 + r) * 128 + c2 * 64 + cc2 * 8);
            }
            CP_COMMIT();
            CP_WAIT1();
        } else {
            CP_WAIT0();
        }
        __syncthreads();
        gemm_chunk_mma(acc, sbase + c * 18432, sbase + 36864 + (s & 1) * 18432,
                       wm, wn, a_lane_off, b_lane_off);
        __syncthreads();
        if (c == 1) {
            stage_acc<true>(smem, acc, bias + yb * 128, 1.0f, wm, wn, g, t);
            __syncthreads();
            #pragma unroll
            for (int it = 0; it < 8; ++it) {
                int idx = tid + it * 256;
                int row = idx >> 4, seg = idx & 15;
                uint4 v = *(const uint4*)(smem + SM_STG + row * 272 + seg * 16);
                *(uint4*)(g_h1_bf + (size_t)(m0 + row) * HID + yb * 128 + seg * 8) = v;
            }
            __syncthreads();
        }
    }
}

// ---------------- fc2 streaming GEMM (K=512, triple-buffered) + residual -------
__global__ void __launch_bounds__(256, 2)
gemm_fc2(const float* __restrict__ bias, float* __restrict__ outp) {
    extern __shared__ char smem[];
    const uint32_t sbase = smem_u32(smem);
    const int m0 = blockIdx.x * 128;
    const int tid  = threadIdx.x;
    const int wid  = tid >> 5;
    const int lane = tid & 31;
    const int g = lane >> 2;
    const int t = lane & 3;
    const int wm = (wid >> 1) * 32;
    const int wn = (wid & 1) * 64;
    const uint32_t a_lane_off = ((lane & 7) + ((lane >> 3) & 1) * 8) * 144 + (lane >> 4) * 16;
    const uint32_t b_lane_off = (((lane >> 4) & 1) * 8 + (lane & 7)) * 144 + ((lane >> 3) & 1) * 16;

    float acc[2][8][4];
    zero_acc(acc);

    #pragma unroll
    for (int pc = 0; pc < 2; ++pc) {
        #pragma unroll
        for (int it = 0; it < 4; ++it) {
            int idx = tid + it * 256;
            int r = idx >> 3, cc = idx & 7;
            uint32_t da = sbase + pc * 36864 + r * 144 + cc * 16;
            CP_ASYNC16(da, g_h1_bf + (size_t)(m0 + r) * 512 + pc * 64 + cc * 8);
            CP_ASYNC16(da + 18432, g_fc2w + (size_t)r * 512 + pc * 64 + cc * 8);
        }
        CP_COMMIT();
    }

    #pragma unroll 1
    for (int c = 0; c < 8; ++c) {
        if (c + 2 < 8) {
            int k0 = (c + 2) * 64;
            int sel = (c + 2) % 3;
            #pragma unroll
            for (int it = 0; it < 4; ++it) {
                int idx = tid + it * 256;
                int r = idx >> 3, cc = idx & 7;
                uint32_t da = sbase + sel * 36864 + r * 144 + cc * 16;
                CP_ASYNC16(da, g_h1_bf + (size_t)(m0 + r) * 512 + k0 + cc * 8);
                CP_ASYNC16(da + 18432, g_fc2w + (size_t)r * 512 + k0 + cc * 8);
            }
            CP_COMMIT();
            CP_WAIT2();
        } else if (c + 1 < 8) {
            CP_WAIT1();
        } else {
            CP_WAIT0();
        }
        __syncthreads();
        uint32_t base = sbase + (c % 3) * 36864;
        gemm_chunk_mma(acc, base, base + 18432, wm, wn, a_lane_off, b_lane_off);
        __syncthreads();
    }
    #pragma unroll
    for (int mi = 0; mi < 2; ++mi)
        #pragma unroll
        for (int half = 0; half < 2; ++half) {
            int m = m0 + wm + mi * 16 + g + half * 8;
            #pragma unroll
            for (int ni = 0; ni < 8; ++ni) {
                int ol = wn + ni * 8 + 2 * t;
                float2 xr = *(const float2*)(g_xres + (size_t)m * CC + ol);
                float2 v;
                v.x = acc[mi][ni][half*2+0] + bias[ol]     + xr.x;
                v.y = acc[mi][ni][half*2+1] + bias[ol + 1] + xr.y;
                *(float2*)(outp + (size_t)m * CC + ol) = v;
            }
        }
}

// ---------------- proj + un-shift scatter + residual + LN2 fused ----------------
__global__ void __launch_bounds__(256, 2)
proj_ln2(const float* __restrict__ bias, const float* __restrict__ xin,
         const float* __restrict__ n2w, const float* __restrict__ n2b) {
    extern __shared__ char smem[];
    const uint32_t sbase = smem_u32(smem);
    const int m0 = blockIdx.x * 128;
    const int tid  = threadIdx.x;
    const int wid  = tid >> 5;
    const int lane = tid & 31;
    const int g = lane >> 2;
    const int t = lane & 3;
    const int wm = (wid >> 1) * 32;
    const int wn = (wid & 1) * 64;
    const uint32_t a_lane_off = ((lane & 7) + ((lane >> 3) & 1) * 8) * 144 + (lane >> 4) * 16;
    const uint32_t b_lane_off = (((lane >> 4) & 1) * 8 + (lane & 7)) * 144 + ((lane >> 3) & 1) * 16;

    #pragma unroll
    for (int it = 0; it < 8; ++it) {
        int idx = tid + it * 256;
        int r = idx >> 4, cc = idx & 15;
        CP_ASYNC16(sbase + (cc >> 3) * 18432 + r * 144 + (cc & 7) * 16,
                   g_obuf_bf + (size_t)(m0 + r) * 128 + cc * 8);
    }
    #pragma unroll
    for (int it = 0; it < 4; ++it) {
        int idx = tid + it * 256;
        int r = idx >> 3, cc2 = idx & 7;
        CP_ASYNC16(sbase + 36864 + r * 144 + cc2 * 16, g_projw + (size_t)r * 128 + cc2 * 8);
    }
    CP_COMMIT();

    float acc[2][8][4];
    zero_acc(acc);
    #pragma unroll 1
    for (int s = 0; s < 2; ++s) {
        if (s == 0) {
            #pragma unroll
            for (int it = 0; it < 4; ++it) {
                int idx = tid + it * 256;
                int r = idx >> 3, cc2 = idx & 7;
                CP_ASYNC16(sbase + 36864 + 18432 + r * 144 + cc2 * 16,
                           g_projw + (size_t)r * 128 + 64 + cc2 * 8);
            }
            CP_COMMIT();
            CP_WAIT1();
        } else {
            CP_WAIT0();
        }
        __syncthreads();
        gemm_chunk_mma(acc, sbase + s * 18432, sbase + 36864 + s * 18432,
                       wm, wn, a_lane_off, b_lane_off);
        __syncthreads();
    }

    float* smf  = (float*)smem;
    float* sumA = (float*)(smem + 67584);
    float* sqA  = (float*)(smem + 68608);
    float* stat = (float*)(smem + 69632);
    int*   tokt = (int*)(smem + 70656);

    if (tid < 128) tokt[tid] = tok_of(m0 + tid);

    #pragma unroll
    for (int mi = 0; mi < 2; ++mi)
        #pragma unroll
        for (int half = 0; half < 2; ++half) {
            int rloc = wm + mi * 16 + g + half * 8;
            int tok = tok_of(m0 + rloc);
            #pragma unroll
            for (int ni = 0; ni < 8; ++ni) {
                int ol = wn + ni * 8 + 2 * t;
                float2 xr = *(const float2*)(xin + (size_t)tok * CC + ol);
                float2 v;
                v.x = acc[mi][ni][half*2+0] + bias[ol]     + xr.x;
                v.y = acc[mi][ni][half*2+1] + bias[ol + 1] + xr.y;
                *(float2*)(g_xres + (size_t)tok * CC + ol) = v;
                *(float2*)(smf + rloc * 132 + ol) = v;
            }
        }
    __syncthreads();

    {
        int r = tid & 127, hs = tid >> 7;
        const float4* p = (const float4*)(smf + r * 132 + hs * 64);
        float s = 0.0f, q = 0.0f;
        #pragma unroll
        for (int i = 0; i < 16; ++i) {
            float4 f = p[i];
            s += f.x + f.y + f.z + f.w;
            q += f.x*f.x + f.y*f.y + f.z*f.z + f.w*f.w;
        }
        sumA[r * 2 + hs] = s;
        sqA [r * 2 + hs] = q;
    }
    __syncthreads();
    if (tid < 128) {
        float s = sumA[tid * 2] + sumA[tid * 2 + 1];
        float q = sqA [tid * 2] + sqA [tid * 2 + 1];
        float mean = s * (1.0f / 128.0f);
        float var = q * (1.0f / 128.0f) - mean * mean;
        stat[tid] = mean;
        stat[128 + tid] = rsqrtf(var + 1e-5f);
    }
    __syncthreads();

    #pragma unroll 1
    for (int i = 0; i < 16; ++i) {
        int seg = tid + i * 256;
        int r = seg >> 5, c4 = (seg & 31) * 4;
        float4 f = *(const float4*)(smf + r * 132 + c4);
        float mean = stat[r], inv = stat[128 + r];
        float4 wv = *(const float4*)(n2w + c4);
        float4 bv = *(const float4*)(n2b + c4);
        uint2 pk;
        pk.x = pack_bf2((f.x - mean) * inv * wv.x + bv.x, (f.y - mean) * inv * wv.y + bv.y);
        pk.y = pack_bf2((f.z - mean) * inv * wv.z + bv.z, (f.w - mean) * inv * wv.w + bv.w);
        *(uint2*)(g_y_bf + (size_t)tokt[r] * CC + c4) = pk;
    }
}

// ---------------- tensor-core windowed attention (cp.async staging) ------------
#define ATT_Q   0
#define ATT_K   20480
#define ATT_V   40960
#define ATT_SM  61440

__global__ void __launch_bounds__(256, 2)
attn_kernel() {
    extern __shared__ char smem[];
    const uint32_t sbase = smem_u32(smem);

    int bn = blockIdx.x;
    int tid = threadIdx.x;
    int wid = tid >> 5, lane = tid & 31;
    int h = wid >> 1, wp = wid & 1;
    int g = lane >> 2, t = lane & 3;

    {
        const __nv_bfloat16* qg = g_q_bf + (size_t)bn * (NH4*NN*HD32);
        const __nv_bfloat16* kg = g_k_bf + (size_t)bn * (NH4*NN*HD32);
        const __nv_bfloat16* vg = g_v_bf + (size_t)bn * (NH4*NN*HD32);
        if (tid < 196) {
            int tok = tid >> 2, seg = tid & 3;
            #pragma unroll
            for (int hh = 0; hh < 4; ++hh) {
                uint32_t doff = (hh * 64 + tok) * 80 + seg * 16;
                size_t soff = (size_t)(hh * 196 + tid) * 8;
                CP_ASYNC16(sbase + ATT_Q + doff, qg + soff);
                CP_ASYNC16(sbase + ATT_K + doff, kg + soff);
                CP_ASYNC16(sbase + ATT_V + doff, vg + soff);
            }
        }
        CP_COMMIT();
        uint4 z = {0, 0, 0, 0};
        for (int i = tid; i < 240; i += 256) {
            int hh = i / 60, rem = i - hh * 60;
            int tok = 49 + (rem >> 2), seg = rem & 3;
            uint32_t doff = ((hh * 64 + tok) * 80 + seg * 16);
            *(uint4*)(smem + ATT_Q + doff) = z;
            *(uint4*)(smem + ATT_K + doff) = z;
            *(uint4*)(smem + ATT_V + doff) = z;
        }
        CP_WAIT0();
    }
    __syncthreads();

    const uint32_t qb = sbase + ATT_Q + (h * 64 + wp * 32) * 80;
    const uint32_t kb = sbase + ATT_K + h * 64 * 80;
    const uint32_t vb = sbase + ATT_V + h * 64 * 80;
    const uint32_t a_off = ((lane & 7) + ((lane >> 3) & 1) * 8) * 80 + (lane >> 4) * 16;
    const uint32_t b_off = (((lane >> 4) & 1) * 8 + (lane & 7)) * 80 + ((lane >> 3) & 1) * 16;

    float sacc[2][8][4];
    #pragma unroll
    for (int mi = 0; mi < 2; ++mi)
        #pragma unroll
        for (int ni = 0; ni < 8; ++ni)
            #pragma unroll
            for (int q = 0; q < 4; ++q) sacc[mi][ni][q] = 0.0f;
    #pragma unroll
    for (int kt = 0; kt < 2; ++kt) {
        uint32_t af[2][4];
        #pragma unroll
        for (int mi = 0; mi < 2; ++mi)
            LDSM4(af[mi][0], af[mi][1], af[mi][2], af[mi][3],
                  qb + mi * 16 * 80 + kt * 32 + a_off);
        uint32_t bf[8][2];
        #pragma unroll
        for (int p = 0; p < 4; ++p)
            LDSM4(bf[2*p][0], bf[2*p][1], bf[2*p+1][0], bf[2*p+1][1],
                  kb + p * 16 * 80 + kt * 32 + b_off);
        #pragma unroll
        for (int mi = 0; mi < 2; ++mi)
            #pragma unroll
            for (int ni = 0; ni < 8; ++ni)
                mma_bf16(sacc[mi][ni][0], sacc[mi][ni][1], sacc[mi][ni][2], sacc[mi][ni][3],
                         af[mi][0], af[mi][1], af[mi][2], af[mi][3],
                         bf[ni][0], bf[ni][1]);
    }

    int win = bn & 255;
    int type = (((win >> 4) == 15) ? 2 : 0) | (((win & 15) == 15) ? 1 : 0);
    const float* atbl = g_atbl + ((type * 4 + h) << 12) + 2 * t;
    #pragma unroll
    for (int mi = 0; mi < 2; ++mi) {
        #pragma unroll
        for (int half = 0; half < 2; ++half) {
            int r = wp * 32 + mi * 16 + g + half * 8;
            const float* tp = atbl + r * 64;
            float mx = -1e30f;
            #pragma unroll
            for (int ni = 0; ni < 8; ++ni) {
                float2 tb = *(const float2*)(tp + ni * 8);
                float v0 = sacc[mi][ni][half*2+0] + tb.x;
                float v1 = sacc[mi][ni][half*2+1] + tb.y;
                sacc[mi][ni][half*2+0] = v0;
                sacc[mi][ni][half*2+1] = v1;
                mx = fmaxf(mx, fmaxf(v0, v1));
            }
            mx = fmaxf(mx, __shfl_xor_sync(0xffffffffu, mx, 1));
            mx = fmaxf(mx, __shfl_xor_sync(0xffffffffu, mx, 2));
            float sum = 0.0f;
            #pragma unroll
            for (int ni = 0; ni < 8; ++ni) {
                float e0 = __expf(sacc[mi][ni][half*2+0] - mx);
                float e1 = __expf(sacc[mi][ni][half*2+1] - mx);
                sacc[mi][ni][half*2+0] = e0;
                sacc[mi][ni][half*2+1] = e1;
                sum += e0 + e1;
            }
            sum += __shfl_xor_sync(0xffffffffu, sum, 1);
            sum += __shfl_xor_sync(0xffffffffu, sum, 2);
            float inv = 1.0f / sum;
            #pragma unroll
            for (int ni = 0; ni < 8; ++ni) {
                sacc[mi][ni][half*2+0] *= inv;
                sacc[mi][ni][half*2+1] *= inv;
            }
        }
    }

    float oacc[2][4][4];
    #pragma unroll
    for (int mi = 0; mi < 2; ++mi)
        #pragma unroll
        for (int nd = 0; nd < 4; ++nd)
            #pragma unroll
            for (int q = 0; q < 4; ++q) oacc[mi][nd][q] = 0.0f;
    #pragma unroll
    for (int kt = 0; kt < 4; ++kt) {
        uint32_t pa[2][4];
        #pragma unroll
        for (int mi = 0; mi < 2; ++mi) {
            pa[mi][0] = pack_bf2(sacc[mi][2*kt][0],   sacc[mi][2*kt][1]);
            pa[mi][1] = pack_bf2(sacc[mi][2*kt][2],   sacc[mi][2*kt][3]);
            pa[mi][2] = pack_bf2(sacc[mi][2*kt+1][0], sacc[mi][2*kt+1][1]);
            pa[mi][3] = pack_bf2(sacc[mi][2*kt+1][2], sacc[mi][2*kt+1][3]);
        }
        uint32_t vf[4][2];
        #pragma unroll
        for (int dh = 0; dh < 2; ++dh) {
            uint32_t r0, r1, r2, r3;
            LDSM4T(r0, r1, r2, r3,
                   vb + (kt * 16 + ((lane >> 3) & 1) * 8 + (lane & 7)) * 80
                      + dh * 32 + (lane >> 4) * 16);
            vf[dh*2][0]   = r0; vf[dh*2][1]   = r1;
            vf[dh*2+1][0] = r2; vf[dh*2+1][1] = r3;
        }
        #pragma unroll
        for (int mi = 0; mi < 2; ++mi)
            #pragma unroll
            for (int nd = 0; nd < 4; ++nd)
                mma_bf16(oacc[mi][nd][0], oacc[mi][nd][1], oacc[mi][nd][2], oacc[mi][nd][3],
                         pa[mi][0], pa[mi][1], pa[mi][2], pa[mi][3],
                         vf[nd][0], vf[nd][1]);
    }

    #pragma unroll
    for (int mi = 0; mi < 2; ++mi)
        #pragma unroll
        for (int half = 0; half < 2; ++half) {
            int r = wp * 32 + mi * 16 + g + half * 8;
            if (r < NN) {
                __nv_bfloat16* o = g_obuf_bf + ((size_t)(bn * NN + r)) * CC + h * HD32;
                #pragma unroll
                for (int nd = 0; nd < 4; ++nd)
                    *(uint32_t*)(o + nd * 8 + 2 * t) =
                        pack_bf2(oacc[mi][nd][half*2+0], oacc[mi][nd][half*2+1]);
            }
        }
}

// ---------------- launch ----------------
extern "C" void kernel_launch(void* const* d_in, const int* in_sizes, int n_in,
                              void* d_out, int out_size) {
    const float* x       = (const float*)d_in[0];
    const float* norm1_w = (const float*)d_in[2];
    const float* norm1_b = (const float*)d_in[3];
    const float* qkv_w   = (const float*)d_in[4];
    const float* qkv_b   = (const float*)d_in[5];
    const float* rpb     = (const float*)d_in[6];
    const float* proj_w  = (const float*)d_in[7];
    const float* proj_b  = (const float*)d_in[8];
    const float* norm2_w = (const float*)d_in[9];
    const float* norm2_b = (const float*)d_in[10];
    const float* fc1_w   = (const float*)d_in[11];
    const float* fc1_b   = (const float*)d_in[12];
    const float* fc2_w   = (const float*)d_in[13];
    const float* fc2_b   = (const float*)d_in[14];
    float* out = (float*)d_out;

    cudaFuncSetAttribute(gemm_qkv,   cudaFuncAttributeMaxDynamicSharedMemorySize, SM_QKV);
    cudaFuncSetAttribute(proj_ln2,   cudaFuncAttributeMaxDynamicSharedMemorySize, SM_PROJ);
    cudaFuncSetAttribute(gemm_fc1,   cudaFuncAttributeMaxDynamicSharedMemorySize, SM_FC1);
    cudaFuncSetAttribute(gemm_fc2,   cudaFuncAttributeMaxDynamicSharedMemorySize, SM_FC2);
    cudaFuncSetAttribute(attn_kernel, cudaFuncAttributeMaxDynamicSharedMemorySize, ATT_SM);

    setup_kernel<<<448, 256>>>(qkv_w, proj_w, fc1_w, fc2_w, rpb);
    gemm_qkv<<<MROWS / 128, 256, SM_QKV>>>(qkv_b, x, norm1_w, norm1_b);
    attn_kernel<<<BB * NW, 256, ATT_SM>>>();
    proj_ln2<<<MROWS / 128, 256, SM_PROJ>>>(proj_b, x, norm2_w, norm2_b);
    gemm_fc1<<<MROWS / 128, 256, SM_FC1>>>(fc1_b);
    gemm_fc2<<<MROWS / 128, 256, SM_FC2>>>(fc2_b, out);
}

// round 17
// speedup vs baseline: 1.1308x; 1.1308x over previous
#include <cuda_runtime.h>
#include <cuda_bf16.h>
#include <math.h>
#include <cstdint>

// ---------------- problem constants ----------------
#define HH     112
#define WW     112
#define CC     128
#define SHIFT3 3
#define NH4    4
#define BB     8
#define HID    512
#define NN     49
#define HD32   32
#define NW     256
#define LTOK   (HH*WW)      // 12544
#define MROWS  (BB*NW*NN)   // 100352 = 784*128
#define SCALEF 0.17677669529663687f

// ---------------- scratch ----------------
__device__ __nv_bfloat16 g_obuf_bf[MROWS*CC];
__device__ __nv_bfloat16 g_y_bf   [MROWS*CC];
__device__ __nv_bfloat16 g_h1_bf  [MROWS*HID];
__device__ __nv_bfloat16 g_q_bf   [MROWS*CC];
__device__ __nv_bfloat16 g_k_bf   [MROWS*CC];
__device__ __nv_bfloat16 g_v_bf   [MROWS*CC];
__device__ float g_xres[MROWS*CC];
__device__ __nv_bfloat16 g_qkvw[3*CC*CC];
__device__ __nv_bfloat16 g_projw[CC*CC];
__device__ __nv_bfloat16 g_fc1w[HID*CC];
__device__ __nv_bfloat16 g_fc2w[CC*HID];
__device__ float g_atbl[4*4*64*64];   // [type][head][n][m] bias+mask (+pad=-1e9)

// ---------------- helpers ----------------
__device__ __forceinline__ uint32_t smem_u32(const void* p) {
    uint32_t a;
    asm("{ .reg .u64 t; cvta.to.shared.u64 t, %1; cvt.u32.u64 %0, t; }" : "=r"(a) : "l"(p));
    return a;
}
__device__ __forceinline__ uint32_t pack_bf2(float lo, float hi) {
    __nv_bfloat162 v = __floats2bfloat162_rn(lo, hi);
    return *(uint32_t*)&v;
}
// fast gelu: tanh form, MUFU-only (EX2 + RCP); overflow-safe (e->inf => th->1)
__device__ __forceinline__ float gelu_f(float x) {
    float u2 = 2.0f * x * (0.7978845608028654f + 0.0356774081f * (x * x));
    float e = __expf(u2);
    float th = 1.0f - __fdividef(2.0f, e + 1.0f);
    return 0.5f * x * (1.0f + th);
}
__device__ __forceinline__ void mma_bf16(float& c0, float& c1, float& c2, float& c3,
                                         uint32_t a0, uint32_t a1, uint32_t a2, uint32_t a3,
                                         uint32_t b0, uint32_t b1) {
    asm volatile("mma.sync.aligned.m16n8k16.row.col.f32.bf16.bf16.f32 "
                 "{%0,%1,%2,%3}, {%4,%5,%6,%7}, {%8,%9}, {%0,%1,%2,%3};"
                 : "+f"(c0), "+f"(c1), "+f"(c2), "+f"(c3)
                 : "r"(a0), "r"(a1), "r"(a2), "r"(a3), "r"(b0), "r"(b1));
}
#define LDSM4(r0, r1, r2, r3, addr) \
    asm volatile("ldmatrix.sync.aligned.m8n8.x4.shared.b16 {%0,%1,%2,%3}, [%4];" \
                 : "=r"(r0), "=r"(r1), "=r"(r2), "=r"(r3) : "r"(addr))
#define LDSM4T(r0, r1, r2, r3, addr) \
    asm volatile("ldmatrix.sync.aligned.m8n8.x4.trans.shared.b16 {%0,%1,%2,%3}, [%4];" \
                 : "=r"(r0), "=r"(r1), "=r"(r2), "=r"(r3) : "r"(addr))
#define CP_ASYNC16(dst, src) \
    asm volatile("cp.async.cg.shared.global [%0], [%1], 16;" :: "r"(dst), "l"(src))
#define CP_COMMIT() asm volatile("cp.async.commit_group;" ::: "memory")
#define CP_WAIT0()  asm volatile("cp.async.wait_group 0;" ::: "memory")
#define CP_WAIT1()  asm volatile("cp.async.wait_group 1;" ::: "memory")
#define CP_WAIT2()  asm volatile("cp.async.wait_group 2;" ::: "memory")

__device__ __forceinline__ int tok_of(int m) {
    int bn = m / NN, n = m - bn * NN;
    int bi = bn >> 8, win = bn & 255;
    int wi = win >> 4, wj = win & 15;
    int r = n / 7, cq = n - r * 7;
    int ii = wi * 7 + r + SHIFT3;  if (ii >= HH) ii -= HH;
    int jj = wj * 7 + cq + SHIFT3; if (jj >= WW) jj -= WW;
    return bi * LTOK + ii * WW + jj;
}
__device__ __forceinline__ int regionf(int i) { return (i < 105) ? 0 : ((i < 109) ? 1 : 2); }

// ---------------- merged setup: weight cvt + attention table ----------------
__global__ void setup_kernel(const float* __restrict__ qkv, const float* __restrict__ proj,
                             const float* __restrict__ fc1, const float* __restrict__ fc2,
                             const float* __restrict__ rpb) {
    int b = blockIdx.x;
    if (b < 192) {
        int i = (b * 256 + threadIdx.x) * 4;
        const float* src;
        __nv_bfloat16* dst;
        int off;
        if (i < 49152)       { src = qkv;  dst = g_qkvw;  off = i; }
        else if (i < 65536)  { src = proj; dst = g_projw; off = i - 49152; }
        else if (i < 131072) { src = fc1;  dst = g_fc1w;  off = i - 65536; }
        else                 { src = fc2;  dst = g_fc2w;  off = i - 131072; }
        float4 v = *(const float4*)(src + off);
        uint2 pk;
        pk.x = pack_bf2(v.x, v.y);
        pk.y = pack_bf2(v.z, v.w);
        *(uint2*)(dst + off) = pk;
    } else {
        int i = (b - 192) * 256 + threadIdx.x;   // 65536 entries
        int m = i & 63, n = (i >> 6) & 63, h = (i >> 12) & 3, ty = i >> 14;
        float v;
        if (n < NN && m < NN) {
            int r1 = n / 7, c1 = n % 7, r2 = m / 7, c2 = m % 7;
            int wiq = (ty >> 1) ? 15 : 0, wjq = (ty & 1) ? 15 : 0;
            int reg1 = regionf(wiq * 7 + r1) * 3 + regionf(wjq * 7 + c1);
            int reg2 = regionf(wiq * 7 + r2) * 3 + regionf(wjq * 7 + c2);
            v = rpb[((r1 - r2 + 6) * 13 + (c1 - c2 + 6)) * NH4 + h];
            if (reg1 != reg2) v -= 100.0f;
        } else {
            v = -1e9f;
        }
        g_atbl[i] = v;
    }
}

// =====================================================================
// GEMM machinery: 128x128 tile, 8 warps (4m x 2n), ldmatrix + mma
// =====================================================================
#define SM_PROJ 73728
#define SM_STG  73728       // staging region offset (qkv/fc1)
#define SM_QKV  108544      // 73728 + 128*272
#define SM_FC1  108544
#define SM_FC2  110592      // 3 x 36864

__device__ __forceinline__ void zero_acc(float acc[2][8][4]) {
    #pragma unroll
    for (int mi = 0; mi < 2; ++mi)
        #pragma unroll
        for (int ni = 0; ni < 8; ++ni)
            #pragma unroll
            for (int q = 0; q < 4; ++q) acc[mi][ni][q] = 0.0f;
}

__device__ __forceinline__ void gemm_chunk_mma(
    float acc[2][8][4], uint32_t Ab, uint32_t Bb,
    int wm, int wn, uint32_t a_lane_off, uint32_t b_lane_off) {
    #pragma unroll
    for (int kk2 = 0; kk2 < 32; kk2 += 8) {
        uint32_t af[2][4];
        #pragma unroll
        for (int mi = 0; mi < 2; ++mi)
            LDSM4(af[mi][0], af[mi][1], af[mi][2], af[mi][3],
                  Ab + (wm + mi * 16) * 144 + kk2 * 4 + a_lane_off);
        uint32_t bf[8][2];
        #pragma unroll
        for (int p = 0; p < 4; ++p)
            LDSM4(bf[2*p][0], bf[2*p][1], bf[2*p+1][0], bf[2*p+1][1],
                  Bb + (wn + p * 16) * 144 + kk2 * 4 + b_lane_off);
        #pragma unroll
        for (int mi = 0; mi < 2; ++mi)
            #pragma unroll
            for (int ni = 0; ni < 8; ++ni)
                mma_bf16(acc[mi][ni][0], acc[mi][ni][1], acc[mi][ni][2], acc[mi][ni][3],
                         af[mi][0], af[mi][1], af[mi][2], af[mi][3],
                         bf[ni][0], bf[ni][1]);
    }
}

// write acc (+bias, optional gelu/scale) into 272B-stride staging tile
template<bool GELU>
__device__ __forceinline__ void stage_acc(
    char* smem, float acc[2][8][4], const float* bias_blk, float scl,
    int wm, int wn, int g, int t) {
    #pragma unroll
    for (int mi = 0; mi < 2; ++mi)
        #pragma unroll
        for (int half = 0; half < 2; ++half) {
            int row = wm + mi * 16 + g + half * 8;
            #pragma unroll
            for (int ni = 0; ni < 8; ++ni) {
                int ol = wn + ni * 8 + 2 * t;
                float a = acc[mi][ni][half*2+0] + bias_blk[ol];
                float b = acc[mi][ni][half*2+1] + bias_blk[ol + 1];
                if (GELU) {
                    a = gelu_f(a);
                    b = gelu_f(b);
                } else {
                    a *= scl; b *= scl;
                }
                *(uint32_t*)(smem + SM_STG + row * 272 + ol * 2) = pack_bf2(a, b);
            }
        }
}

// ---------------- QKV GEMM with fused LN1 gather; staged wide stores -----------
__global__ void __launch_bounds__(256, 2)
gemm_qkv(const float* __restrict__ bias, const float* __restrict__ xin,
         const float* __restrict__ n1w, const float* __restrict__ n1b) {
    extern __shared__ char smem[];
    const uint32_t sbase = smem_u32(smem);
    const int m0 = blockIdx.x * 128;
    const int tid  = threadIdx.x;
    const int wid  = tid >> 5;
    const int lane = tid & 31;
    const int g = lane >> 2;
    const int t = lane & 3;
    const int wm = (wid >> 1) * 32;
    const int wn = (wid & 1) * 64;
    const uint32_t a_lane_off = ((lane & 7) + ((lane >> 3) & 1) * 8) * 144 + (lane >> 4) * 16;
    const uint32_t b_lane_off = (((lane >> 4) & 1) * 8 + (lane & 7)) * 144 + ((lane >> 3) & 1) * 16;

    #pragma unroll
    for (int it = 0; it < 4; ++it) {
        int idx = tid + it * 256;
        int r = idx >> 3, cc2 = idx & 7;
        CP_ASYNC16(sbase + 36864 + r * 144 + cc2 * 16, g_qkvw + (size_t)r * 128 + cc2 * 8);
    }
    CP_COMMIT();

    // fused LN1 + shift-gather into A tile
    {
        float4 wv = ((const float4*)n1w)[lane];
        float4 bv = ((const float4*)n1b)[lane];
        #pragma unroll 4
        for (int rr = 0; rr < 16; ++rr) {
            int r = wid * 16 + rr;
            int tok = tok_of(m0 + r);
            float4 v = *(const float4*)(xin + (size_t)tok * CC + lane * 4);
            float s = v.x + v.y + v.z + v.w;
            #pragma unroll
            for (int o = 16; o; o >>= 1) s += __shfl_xor_sync(0xffffffffu, s, o);
            float mean = s * (1.0f / 128.0f);
            float dx = v.x - mean, dy = v.y - mean, dz = v.z - mean, dw = v.w - mean;
            float q = dx*dx + dy*dy + dz*dz + dw*dw;
            #pragma unroll
            for (int o = 16; o; o >>= 1) q += __shfl_xor_sync(0xffffffffu, q, o);
            float inv = rsqrtf(q * (1.0f / 128.0f) + 1e-5f);
            uint2 pk;
            pk.x = pack_bf2(dx * inv * wv.x + bv.x, dy * inv * wv.y + bv.y);
            pk.y = pack_bf2(dz * inv * wv.z + bv.z, dw * inv * wv.w + bv.w);
            *(uint2*)(smem + (lane >> 4) * 18432 + r * 144 + (lane & 15) * 8) = *(uint2*)&pk;
        }
    }

    float acc[2][8][4];
    #pragma unroll 1
    for (int s = 0; s < 6; ++s) {
        int c = s & 1, yb = s >> 1;
        if (c == 0) zero_acc(acc);
        if (s + 1 < 6) {
            int yb2 = (s + 1) >> 1, c2 = (s + 1) & 1;
            #pragma unroll
            for (int it = 0; it < 4; ++it) {
                int idx = tid + it * 256;
                int r = idx >> 3, cc2 = idx & 7;
                CP_ASYNC16(sbase + 36864 + ((s + 1) & 1) * 18432 + r * 144 + cc2 * 16,
                           g_qkvw + (size_t)(yb2 * 128 + r) * 128 + c2 * 64 + cc2 * 8);
            }
            CP_COMMIT();
            CP_WAIT1();
        } else {
            CP_WAIT0();
        }
        __syncthreads();
        gemm_chunk_mma(acc, sbase + c * 18432, sbase + 36864 + (s & 1) * 18432,
                       wm, wn, a_lane_off, b_lane_off);
        __syncthreads();
        if (c == 1) {
            __nv_bfloat16* dst = (yb == 0) ? g_q_bf : (yb == 1) ? g_k_bf : g_v_bf;
            stage_acc<false>(smem, acc, bias + yb * 128, (yb == 0) ? SCALEF : 1.0f,
                             wm, wn, g, t);
            __syncthreads();
            // cooperative wide stores: 128 rows x 16 uint4 segments
            #pragma unroll
            for (int it = 0; it < 8; ++it) {
                int idx = tid + it * 256;
                int row = idx >> 4, seg = idx & 15;
                uint4 v = *(const uint4*)(smem + SM_STG + row * 272 + seg * 16);
                int m = m0 + row;
                int bn = m / NN, n = m - bn * NN;
                int hh = seg >> 2, dd = (seg & 3) * 8;
                *(uint4*)(dst + (size_t)(bn * NH4 + hh) * (NN * HD32) + n * HD32 + dd) = v;
            }
            __syncthreads();
        }
    }
}

// ---------------- fc1 GEMM: A resident, 4 weight blocks, gelu, staged stores ---
__global__ void __launch_bounds__(256, 2)
gemm_fc1(const float* __restrict__ bias) {
    extern __shared__ char smem[];
    const uint32_t sbase = smem_u32(smem);
    const int m0 = blockIdx.x * 128;
    const int tid  = threadIdx.x;
    const int wid  = tid >> 5;
    const int lane = tid & 31;
    const int g = lane >> 2;
    const int t = lane & 3;
    const int wm = (wid >> 1) * 32;
    const int wn = (wid & 1) * 64;
    const uint32_t a_lane_off = ((lane & 7) + ((lane >> 3) & 1) * 8) * 144 + (lane >> 4) * 16;
    const uint32_t b_lane_off = (((lane >> 4) & 1) * 8 + (lane & 7)) * 144 + ((lane >> 3) & 1) * 16;

    #pragma unroll
    for (int it = 0; it < 8; ++it) {
        int idx = tid + it * 256;
        int r = idx >> 4, cc = idx & 15;
        CP_ASYNC16(sbase + (cc >> 3) * 18432 + r * 144 + (cc & 7) * 16,
                   g_y_bf + (size_t)(m0 + r) * 128 + cc * 8);
    }
    #pragma unroll
    for (int it = 0; it < 4; ++it) {
        int idx = tid + it * 256;
        int r = idx >> 3, cc2 = idx & 7;
        CP_ASYNC16(sbase + 36864 + r * 144 + cc2 * 16, g_fc1w + (size_t)r * 128 + cc2 * 8);
    }
    CP_COMMIT();

    float acc[2][8][4];
    #pragma unroll 1
    for (int s = 0; s < 8; ++s) {
        int c = s & 1, yb = s >> 1;
        if (c == 0) zero_acc(acc);
        if (s + 1 < 8) {
            int yb2 = (s + 1) >> 1, c2 = (s + 1) & 1;
            #pragma unroll
            for (int it = 0; it < 4; ++it) {
                int idx = tid + it * 256;
                int r = idx >> 3, cc2 = idx & 7;
                CP_ASYNC16(sbase + 36864 + ((s + 1) & 1) * 18432 + r * 144 + cc2 * 16,
                           g_fc1w + (size_t)(yb2 * 128 + r) * 128 + c2 * 64 + cc2 * 8);
            }
            CP_COMMIT();
            CP_WAIT1();
        } else {
            CP_WAIT0();
        }
        __syncthreads();
        gemm_chunk_mma(acc, sbase + c * 18432, sbase + 36864 + (s & 1) * 18432,
                       wm, wn, a_lane_off, b_lane_off);
        __syncthreads();
        if (c == 1) {
            stage_acc<true>(smem, acc, bias + yb * 128, 1.0f, wm, wn, g, t);
            __syncthreads();
            #pragma unroll
            for (int it = 0; it < 8; ++it) {
                int idx = tid + it * 256;
                int row = idx >> 4, seg = idx & 15;
                uint4 v = *(const uint4*)(smem + SM_STG + row * 272 + seg * 16);
                *(uint4*)(g_h1_bf + (size_t)(m0 + row) * HID + yb * 128 + seg * 8) = v;
            }
            __syncthreads();
        }
    }
}

// ---------------- fc2 streaming GEMM (K=512, triple-buffered) + residual -------
__global__ void __launch_bounds__(256, 2)
gemm_fc2(const float* __restrict__ bias, float* __restrict__ outp) {
    extern __shared__ char smem[];
    const uint32_t sbase = smem_u32(smem);
    const int m0 = blockIdx.x * 128;
    const int tid  = threadIdx.x;
    const int wid  = tid >> 5;
    const int lane = tid & 31;
    const int g = lane >> 2;
    const int t = lane & 3;
    const int wm = (wid >> 1) * 32;
    const int wn = (wid & 1) * 64;
    const uint32_t a_lane_off = ((lane & 7) + ((lane >> 3) & 1) * 8) * 144 + (lane >> 4) * 16;
    const uint32_t b_lane_off = (((lane >> 4) & 1) * 8 + (lane & 7)) * 144 + ((lane >> 3) & 1) * 16;

    float acc[2][8][4];
    zero_acc(acc);

    #pragma unroll
    for (int pc = 0; pc < 2; ++pc) {
        #pragma unroll
        for (int it = 0; it < 4; ++it) {
            int idx = tid + it * 256;
            int r = idx >> 3, cc = idx & 7;
            uint32_t da = sbase + pc * 36864 + r * 144 + cc * 16;
            CP_ASYNC16(da, g_h1_bf + (size_t)(m0 + r) * 512 + pc * 64 + cc * 8);
            CP_ASYNC16(da + 18432, g_fc2w + (size_t)r * 512 + pc * 64 + cc * 8);
        }
        CP_COMMIT();
    }

    #pragma unroll 1
    for (int c = 0; c < 8; ++c) {
        if (c + 2 < 8) {
            int k0 = (c + 2) * 64;
            int sel = (c + 2) % 3;
            #pragma unroll
            for (int it = 0; it < 4; ++it) {
                int idx = tid + it * 256;
                int r = idx >> 3, cc = idx & 7;
                uint32_t da = sbase + sel * 36864 + r * 144 + cc * 16;
                CP_ASYNC16(da, g_h1_bf + (size_t)(m0 + r) * 512 + k0 + cc * 8);
                CP_ASYNC16(da + 18432, g_fc2w + (size_t)r * 512 + k0 + cc * 8);
            }
            CP_COMMIT();
            CP_WAIT2();
        } else if (c + 1 < 8) {
            CP_WAIT1();
        } else {
            CP_WAIT0();
        }
        __syncthreads();
        uint32_t base = sbase + (c % 3) * 36864;
        gemm_chunk_mma(acc, base, base + 18432, wm, wn, a_lane_off, b_lane_off);
        __syncthreads();
    }
    #pragma unroll
    for (int mi = 0; mi < 2; ++mi)
        #pragma unroll
        for (int half = 0; half < 2; ++half) {
            int m = m0 + wm + mi * 16 + g + half * 8;
            #pragma unroll
            for (int ni = 0; ni < 8; ++ni) {
                int ol = wn + ni * 8 + 2 * t;
                float2 xr = *(const float2*)(g_xres + (size_t)m * CC + ol);
                float2 v;
                v.x = acc[mi][ni][half*2+0] + bias[ol]     + xr.x;
                v.y = acc[mi][ni][half*2+1] + bias[ol + 1] + xr.y;
                *(float2*)(outp + (size_t)m * CC + ol) = v;
            }
        }
}

// ---------------- proj + un-shift scatter + residual + LN2 fused ----------------
__global__ void __launch_bounds__(256, 2)
proj_ln2(const float* __restrict__ bias, const float* __restrict__ xin,
         const float* __restrict__ n2w, const float* __restrict__ n2b) {
    extern __shared__ char smem[];
    const uint32_t sbase = smem_u32(smem);
    const int m0 = blockIdx.x * 128;
    const int tid  = threadIdx.x;
    const int wid  = tid >> 5;
    const int lane = tid & 31;
    const int g = lane >> 2;
    const int t = lane & 3;
    const int wm = (wid >> 1) * 32;
    const int wn = (wid & 1) * 64;
    const uint32_t a_lane_off = ((lane & 7) + ((lane >> 3) & 1) * 8) * 144 + (lane >> 4) * 16;
    const uint32_t b_lane_off = (((lane >> 4) & 1) * 8 + (lane & 7)) * 144 + ((lane >> 3) & 1) * 16;

    #pragma unroll
    for (int it = 0; it < 8; ++it) {
        int idx = tid + it * 256;
        int r = idx >> 4, cc = idx & 15;
        CP_ASYNC16(sbase + (cc >> 3) * 18432 + r * 144 + (cc & 7) * 16,
                   g_obuf_bf + (size_t)(m0 + r) * 128 + cc * 8);
    }
    #pragma unroll
    for (int it = 0; it < 4; ++it) {
        int idx = tid + it * 256;
        int r = idx >> 3, cc2 = idx & 7;
        CP_ASYNC16(sbase + 36864 + r * 144 + cc2 * 16, g_projw + (size_t)r * 128 + cc2 * 8);
    }
    CP_COMMIT();

    float acc[2][8][4];
    zero_acc(acc);
    #pragma unroll 1
    for (int s = 0; s < 2; ++s) {
        if (s == 0) {
            #pragma unroll
            for (int it = 0; it < 4; ++it) {
                int idx = tid + it * 256;
                int r = idx >> 3, cc2 = idx & 7;
                CP_ASYNC16(sbase + 36864 + 18432 + r * 144 + cc2 * 16,
                           g_projw + (size_t)r * 128 + 64 + cc2 * 8);
            }
            CP_COMMIT();
            CP_WAIT1();
        } else {
            CP_WAIT0();
        }
        __syncthreads();
        gemm_chunk_mma(acc, sbase + s * 18432, sbase + 36864 + s * 18432,
                       wm, wn, a_lane_off, b_lane_off);
        __syncthreads();
    }

    float* smf  = (float*)smem;
    float* sumA = (float*)(smem + 67584);
    float* sqA  = (float*)(smem + 68608);
    float* stat = (float*)(smem + 69632);
    int*   tokt = (int*)(smem + 70656);

    if (tid < 128) tokt[tid] = tok_of(m0 + tid);

    #pragma unroll
    for (int mi = 0; mi < 2; ++mi)
        #pragma unroll
        for (int half = 0; half < 2; ++half) {
            int rloc = wm + mi * 16 + g + half * 8;
            int tok = tok_of(m0 + rloc);
            #pragma unroll
            for (int ni = 0; ni < 8; ++ni) {
                int ol = wn + ni * 8 + 2 * t;
                float2 xr = *(const float2*)(xin + (size_t)tok * CC + ol);
                float2 v;
                v.x = acc[mi][ni][half*2+0] + bias[ol]     + xr.x;
                v.y = acc[mi][ni][half*2+1] + bias[ol + 1] + xr.y;
                *(float2*)(g_xres + (size_t)tok * CC + ol) = v;
                *(float2*)(smf + rloc * 132 + ol) = v;
            }
        }
    __syncthreads();

    {
        int r = tid & 127, hs = tid >> 7;
        const float4* p = (const float4*)(smf + r * 132 + hs * 64);
        float s = 0.0f, q = 0.0f;
        #pragma unroll
        for (int i = 0; i < 16; ++i) {
            float4 f = p[i];
            s += f.x + f.y + f.z + f.w;
            q += f.x*f.x + f.y*f.y + f.z*f.z + f.w*f.w;
        }
        sumA[r * 2 + hs] = s;
        sqA [r * 2 + hs] = q;
    }
    __syncthreads();
    if (tid < 128) {
        float s = sumA[tid * 2] + sumA[tid * 2 + 1];
        float q = sqA [tid * 2] + sqA [tid * 2 + 1];
        float mean = s * (1.0f / 128.0f);
        float var = q * (1.0f / 128.0f) - mean * mean;
        stat[tid] = mean;
        stat[128 + tid] = rsqrtf(var + 1e-5f);
    }
    __syncthreads();

    #pragma unroll 1
    for (int i = 0; i < 16; ++i) {
        int seg = tid + i * 256;
        int r = seg >> 5, c4 = (seg & 31) * 4;
        float4 f = *(const float4*)(smf + r * 132 + c4);
        float mean = stat[r], inv = stat[128 + r];
        float4 wv = *(const float4*)(n2w + c4);
        float4 bv = *(const float4*)(n2b + c4);
        uint2 pk;
        pk.x = pack_bf2((f.x - mean) * inv * wv.x + bv.x, (f.y - mean) * inv * wv.y + bv.y);
        pk.y = pack_bf2((f.z - mean) * inv * wv.z + bv.z, (f.w - mean) * inv * wv.w + bv.w);
        *(uint2*)(g_y_bf + (size_t)tokt[r] * CC + c4) = pk;
    }
}

// ---------------- tensor-core windowed attention (cp.async staging) ------------
#define ATT_Q   0
#define ATT_K   20480
#define ATT_V   40960
#define ATT_SM  61440

__global__ void __launch_bounds__(256, 2)
attn_kernel() {
    extern __shared__ char smem[];
    const uint32_t sbase = smem_u32(smem);

    int bn = blockIdx.x;
    int tid = threadIdx.x;
    int wid = tid >> 5, lane = tid & 31;
    int h = wid >> 1, wp = wid & 1;
    int g = lane >> 2, t = lane & 3;

    {
        const __nv_bfloat16* qg = g_q_bf + (size_t)bn * (NH4*NN*HD32);
        const __nv_bfloat16* kg = g_k_bf + (size_t)bn * (NH4*NN*HD32);
        const __nv_bfloat16* vg = g_v_bf + (size_t)bn * (NH4*NN*HD32);
        if (tid < 196) {
            int tok = tid >> 2, seg = tid & 3;
            #pragma unroll
            for (int hh = 0; hh < 4; ++hh) {
                uint32_t doff = (hh * 64 + tok) * 80 + seg * 16;
                size_t soff = (size_t)(hh * 196 + tid) * 8;
                CP_ASYNC16(sbase + ATT_Q + doff, qg + soff);
                CP_ASYNC16(sbase + ATT_K + doff, kg + soff);
                CP_ASYNC16(sbase + ATT_V + doff, vg + soff);
            }
        }
        CP_COMMIT();
        uint4 z = {0, 0, 0, 0};
        for (int i = tid; i < 240; i += 256) {
            int hh = i / 60, rem = i - hh * 60;
            int tok = 49 + (rem >> 2), seg = rem & 3;
            uint32_t doff = ((hh * 64 + tok) * 80 + seg * 16);
            *(uint4*)(smem + ATT_Q + doff) = z;
            *(uint4*)(smem + ATT_K + doff) = z;
            *(uint4*)(smem + ATT_V + doff) = z;
        }
        CP_WAIT0();
    }
    __syncthreads();

    const uint32_t qb = sbase + ATT_Q + (h * 64 + wp * 32) * 80;
    const uint32_t kb = sbase + ATT_K + h * 64 * 80;
    const uint32_t vb = sbase + ATT_V + h * 64 * 80;
    const uint32_t a_off = ((lane & 7) + ((lane >> 3) & 1) * 8) * 80 + (lane >> 4) * 16;
    const uint32_t b_off = (((lane >> 4) & 1) * 8 + (lane & 7)) * 80 + ((lane >> 3) & 1) * 16;

    float sacc[2][8][4];
    #pragma unroll
    for (int mi = 0; mi < 2; ++mi)
        #pragma unroll
        for (int ni = 0; ni < 8; ++ni)
            #pragma unroll
            for (int q = 0; q < 4; ++q) sacc[mi][ni][q] = 0.0f;
    #pragma unroll
    for (int kt = 0; kt < 2; ++kt) {
        uint32_t af[2][4];
        #pragma unroll
        for (int mi = 0; mi < 2; ++mi)
            LDSM4(af[mi][0], af[mi][1], af[mi][2], af[mi][3],
                  qb + mi * 16 * 80 + kt * 32 + a_off);
        uint32_t bf[8][2];
        #pragma unroll
        for (int p = 0; p < 4; ++p)
            LDSM4(bf[2*p][0], bf[2*p][1], bf[2*p+1][0], bf[2*p+1][1],
                  kb + p * 16 * 80 + kt * 32 + b_off);
        #pragma unroll
        for (int mi = 0; mi < 2; ++mi)
            #pragma unroll
            for (int ni = 0; ni < 8; ++ni)
                mma_bf16(sacc[mi][ni][0], sacc[mi][ni][1], sacc[mi][ni][2], sacc[mi][ni][3],
                         af[mi][0], af[mi][1], af[mi][2], af[mi][3],
                         bf[ni][0], bf[ni][1]);
    }

    int win = bn & 255;
    int type = (((win >> 4) == 15) ? 2 : 0) | (((win & 15) == 15) ? 1 : 0);
    const float* atbl = g_atbl + ((type * 4 + h) << 12) + 2 * t;
    #pragma unroll
    for (int mi = 0; mi < 2; ++mi) {
        #pragma unroll
        for (int half = 0; half < 2; ++half) {
            int r = wp * 32 + mi * 16 + g + half * 8;
            const float* tp = atbl + r * 64;
            float mx = -1e30f;
            #pragma unroll
            for (int ni = 0; ni < 8; ++ni) {
                float2 tb = *(const float2*)(tp + ni * 8);
                float v0 = sacc[mi][ni][half*2+0] + tb.x;
                float v1 = sacc[mi][ni][half*2+1] + tb.y;
                sacc[mi][ni][half*2+0] = v0;
                sacc[mi][ni][half*2+1] = v1;
                mx = fmaxf(mx, fmaxf(v0, v1));
            }
            mx = fmaxf(mx, __shfl_xor_sync(0xffffffffu, mx, 1));
            mx = fmaxf(mx, __shfl_xor_sync(0xffffffffu, mx, 2));
            float sum = 0.0f;
            #pragma unroll
            for (int ni = 0; ni < 8; ++ni) {
                float e0 = __expf(sacc[mi][ni][half*2+0] - mx);
                float e1 = __expf(sacc[mi][ni][half*2+1] - mx);
                sacc[mi][ni][half*2+0] = e0;
                sacc[mi][ni][half*2+1] = e1;
                sum += e0 + e1;
            }
            sum += __shfl_xor_sync(0xffffffffu, sum, 1);
            sum += __shfl_xor_sync(0xffffffffu, sum, 2);
            float inv = 1.0f / sum;
            #pragma unroll
            for (int ni = 0; ni < 8; ++ni) {
                sacc[mi][ni][half*2+0] *= inv;
                sacc[mi][ni][half*2+1] *= inv;
            }
        }
    }

    float oacc[2][4][4];
    #pragma unroll
    for (int mi = 0; mi < 2; ++mi)
        #pragma unroll
        for (int nd = 0; nd < 4; ++nd)
            #pragma unroll
            for (int q = 0; q < 4; ++q) oacc[mi][nd][q] = 0.0f;
    #pragma unroll
    for (int kt = 0; kt < 4; ++kt) {
        uint32_t pa[2][4];
        #pragma unroll
        for (int mi = 0; mi < 2; ++mi) {
            pa[mi][0] = pack_bf2(sacc[mi][2*kt][0],   sacc[mi][2*kt][1]);
            pa[mi][1] = pack_bf2(sacc[mi][2*kt][2],   sacc[mi][2*kt][3]);
            pa[mi][2] = pack_bf2(sacc[mi][2*kt+1][0], sacc[mi][2*kt+1][1]);
            pa[mi][3] = pack_bf2(sacc[mi][2*kt+1][2], sacc[mi][2*kt+1][3]);
        }
        uint32_t vf[4][2];
        #pragma unroll
        for (int dh = 0; dh < 2; ++dh) {
            uint32_t r0, r1, r2, r3;
            LDSM4T(r0, r1, r2, r3,
                   vb + (kt * 16 + ((lane >> 3) & 1) * 8 + (lane & 7)) * 80
                      + dh * 32 + (lane >> 4) * 16);
            vf[dh*2][0]   = r0; vf[dh*2][1]   = r1;
            vf[dh*2+1][0] = r2; vf[dh*2+1][1] = r3;
        }
        #pragma unroll
        for (int mi = 0; mi < 2; ++mi)
            #pragma unroll
            for (int nd = 0; nd < 4; ++nd)
                mma_bf16(oacc[mi][nd][0], oacc[mi][nd][1], oacc[mi][nd][2], oacc[mi][nd][3],
                         pa[mi][0], pa[mi][1], pa[mi][2], pa[mi][3],
                         vf[nd][0], vf[nd][1]);
    }

    #pragma unroll
    for (int mi = 0; mi < 2; ++mi)
        #pragma unroll
        for (int half = 0; half < 2; ++half) {
            int r = wp * 32 + mi * 16 + g + half * 8;
            if (r < NN) {
                __nv_bfloat16* o = g_obuf_bf + ((size_t)(bn * NN + r)) * CC + h * HD32;
                #pragma unroll
                for (int nd = 0; nd < 4; ++nd)
                    *(uint32_t*)(o + nd * 8 + 2 * t) =
                        pack_bf2(oacc[mi][nd][half*2+0], oacc[mi][nd][half*2+1]);
            }
        }
}

// ---------------- launch ----------------
extern "C" void kernel_launch(void* const* d_in, const int* in_sizes, int n_in,
                              void* d_out, int out_size) {
    const float* x       = (const float*)d_in[0];
    const float* norm1_w = (const float*)d_in[2];
    const float* norm1_b = (const float*)d_in[3];
    const float* qkv_w   = (const float*)d_in[4];
    const float* qkv_b   = (const float*)d_in[5];
    const float* rpb     = (const float*)d_in[6];
    const float* proj_w  = (const float*)d_in[7];
    const float* proj_b  = (const float*)d_in[8];
    const float* norm2_w = (const float*)d_in[9];
    const float* norm2_b = (const float*)d_in[10];
    const float* fc1_w   = (const float*)d_in[11];
    const float* fc1_b   = (const float*)d_in[12];
    const float* fc2_w   = (const float*)d_in[13];
    const float* fc2_b   = (const float*)d_in[14];
    float* out = (float*)d_out;

    cudaFuncSetAttribute(gemm_qkv,   cudaFuncAttributeMaxDynamicSharedMemorySize, SM_QKV);
    cudaFuncSetAttribute(proj_ln2,   cudaFuncAttributeMaxDynamicSharedMemorySize, SM_PROJ);
    cudaFuncSetAttribute(gemm_fc1,   cudaFuncAttributeMaxDynamicSharedMemorySize, SM_FC1);
    cudaFuncSetAttribute(gemm_fc2,   cudaFuncAttributeMaxDynamicSharedMemorySize, SM_FC2);
    cudaFuncSetAttribute(attn_kernel, cudaFuncAttributeMaxDynamicSharedMemorySize, ATT_SM);

    setup_kernel<<<448, 256>>>(qkv_w, proj_w, fc1_w, fc2_w, rpb);
    gemm_qkv<<<MROWS / 128, 256, SM_QKV>>>(qkv_b, x, norm1_w, norm1_b);
    attn_kernel<<<BB * NW, 256, ATT_SM>>>();
    proj_ln2<<<MROWS / 128, 256, SM_PROJ>>>(proj_b, x, norm2_w, norm2_b);
    gemm_fc1<<<MROWS / 128, 256, SM_FC1>>>(fc1_b);
    gemm_fc2<<<MROWS / 128, 256, SM_FC2>>>(fc2_b, out);
}